// round 14
// baseline (speedup 1.0000x reference)
#include <cuda_runtime.h>
#include <cuda_bf16.h>
#include <cstdint>

#define NREAL 2800
#define NPADN 3000
#define MPAD  3072
#define FIN   8192
#define H1    256
#define H2    128
#define NE    179200
#define KCAT  512

// ---- GEMM2 constants (BK=32) ----
#define RSTR  20
#define PLANE (128 * RSTR)
#define SMEMSZ (2 * 4 * PLANE * 4)  // 80KB
// ---- GEMM1 constants (BK=64) ----
#define RSTR1 36                    // 32 data words + 4 pad (conflict-free)
#define APL   (128 * RSTR1)         // 4608 words
#define BPL   (256 * RSTR1)         // 9216 words
#define WST   (2 * APL + 2 * BPL)   // 27648 words = 108KB
#define SMEM1 (2 * WST * 4)         // 216KB

// ---------------- scratch (device-code references only!) --------------------
__device__ __align__(16) float g_part1[6 * MPAD * H1];
__device__ __align__(16) float g_acc2[MPAD * KCAT];
__device__ __align__(16) __nv_bfloat16 g_wThi[H1 * FIN];
__device__ __align__(16) __nv_bfloat16 g_wTlo[H1 * FIN];
__device__ __align__(16) __nv_bfloat16 g_Ahi[NPADN * KCAT];
__device__ __align__(16) __nv_bfloat16 g_Alo[NPADN * KCAT];
__device__ __align__(16) __nv_bfloat16 g_BThi[KCAT * KCAT];
__device__ __align__(16) __nv_bfloat16 g_BTlo[KCAT * KCAT];
__device__ __align__(16) float g_deg[NPADN];
__device__ __align__(16) float g_dinv[NPADN];
__device__ __align__(16) float g_wedge[NE];
__device__ __align__(16) int   g_cnt[NPADN];
__device__ __align__(16) int   g_cur[NPADN];
__device__ __align__(16) int   g_off[NPADN + 4];
__device__ __align__(16) int   g_bucket[NE];
__device__ int g_is32;

// ---------------- helpers ----------------------------------------------------
__device__ __forceinline__ float sigmoidf_(float x) { return 1.0f / (1.0f + expf(-x)); }

__device__ __forceinline__ void split2(float v, __nv_bfloat16& h, __nv_bfloat16& l) {
    h = __float2bfloat16_rn(v);
    l = __float2bfloat16_rn(v - __bfloat162float(h));
}
__device__ __forceinline__ void split2x2(float a, float b, uint32_t& h2, uint32_t& l2) {
    __nv_bfloat16 ha, la, hb, lb;
    split2(a, ha, la); split2(b, hb, lb);
    __nv_bfloat162 h = __halves2bfloat162(ha, hb);
    __nv_bfloat162 l = __halves2bfloat162(la, lb);
    h2 = *(uint32_t*)&h; l2 = *(uint32_t*)&l;
}
__device__ __forceinline__ int load_idx(const void* ei, int i) {
    if (g_is32) return ((const int*)ei)[i];
    return (int)((const long long*)ei)[i];
}
__device__ __forceinline__ void mma_bf16(float* d, const uint32_t* a,
                                         uint32_t b0, uint32_t b1) {
    asm volatile(
        "mma.sync.aligned.m16n8k16.row.col.f32.bf16.bf16.f32 "
        "{%0,%1,%2,%3}, {%4,%5,%6,%7}, {%8,%9}, {%0,%1,%2,%3};"
        : "+f"(d[0]), "+f"(d[1]), "+f"(d[2]), "+f"(d[3])
        : "r"(a[0]), "r"(a[1]), "r"(a[2]), "r"(a[3]), "r"(b0), "r"(b1));
}
#define LDMX4(r0, r1, r2, r3, a) \
    asm volatile("ldmatrix.sync.aligned.m8n8.x4.shared.b16 {%0,%1,%2,%3}, [%4];" \
                 : "=r"(r0), "=r"(r1), "=r"(r2), "=r"(r3) : "r"(a))
#define CPA16(dst, src, sz) \
    asm volatile("cp.async.ca.shared.global [%0], [%1], 16, %2;" \
                 :: "r"(dst), "l"(src), "r"(sz))
#define CPA_COMMIT() asm volatile("cp.async.commit_group;")
#define CPA_WAIT0()  asm volatile("cp.async.wait_group 0;")

// ---------------- probe + zero (fused) -----------------------------------------
__global__ void k_probe_zero(const void* p) {
    int i = blockIdx.x * blockDim.x + threadIdx.x;
    if (i < NPADN) { g_deg[i] = 0.f; g_cnt[i] = 0; g_cur[i] = 0; }
    if (blockIdx.x == 0) {
        __shared__ int any;
        if (threadIdx.x == 0) any = 0;
        __syncthreads();
        const int* q = (const int*)p;
        int v = 0;
        for (int j = threadIdx.x; j < 4096; j += blockDim.x) v |= q[2 * j + 1];
        if (v) atomicOr(&any, 1);
        __syncthreads();
        if (threadIdx.x == 0) g_is32 = (any != 0) ? 1 : 0;
    }
}

// fc0_w [FIN][H1] -> wT hi/lo [H1][FIN]
__global__ void k_convW(const float* __restrict__ w) {
    __shared__ float tile[32][33];
    int kb = blockIdx.x * 32, jb = blockIdx.y * 32;
    int tx = threadIdx.x & 31, ty = threadIdx.x >> 5;
    #pragma unroll
    for (int r = 0; r < 32; r += 8)
        tile[ty + r][tx] = w[(size_t)(kb + ty + r) * H1 + jb + tx];
    __syncthreads();
    #pragma unroll
    for (int r = 0; r < 32; r += 8) {
        float v = tile[tx][ty + r];
        __nv_bfloat16 h, l; split2(v, h, l);
        size_t o = (size_t)(jb + ty + r) * FIN + kb + tx;
        g_wThi[o] = h; g_wTlo[o] = l;
    }
}

// ---------------- graph preprocessing ------------------------------------------
__global__ void k_edges1(const void* __restrict__ ei,
                         const float* __restrict__ ew) {
    int base = (blockIdx.x * blockDim.x + threadIdx.x) * 2;
    #pragma unroll
    for (int j = 0; j < 2; j++) {
        int e = base + j;
        if (e < NE) {
            int r = load_idx(ei, e);
            int c = load_idx(ei, NE + e);
            if ((unsigned)r < NPADN) atomicAdd(&g_deg[r], ew[e]);
            if ((unsigned)c < NPADN) atomicAdd(&g_cnt[c], 1);
        }
    }
}

__global__ void k_scan() {
    int t = threadIdx.x;
    for (int i = t; i < NPADN; i += 1024) {
        float d = g_deg[i];
        g_dinv[i] = (d > 0.f) ? rsqrtf(d) : 0.f;
    }
    __shared__ int warp_sums[32];
    int i0 = t * 3;
    int v0 = (i0     < NPADN) ? g_cnt[i0]     : 0;
    int v1 = (i0 + 1 < NPADN) ? g_cnt[i0 + 1] : 0;
    int v2 = (i0 + 2 < NPADN) ? g_cnt[i0 + 2] : 0;
    int s = v0 + v1 + v2;
    int lane = t & 31, warp = t >> 5;
    int x = s;
    #pragma unroll
    for (int d = 1; d < 32; d <<= 1) {
        int y = __shfl_up_sync(0xffffffffu, x, d);
        if (lane >= d) x += y;
    }
    if (lane == 31) warp_sums[warp] = x;
    __syncthreads();
    if (warp == 0) {
        int w = warp_sums[lane];
        #pragma unroll
        for (int d = 1; d < 32; d <<= 1) {
            int y = __shfl_up_sync(0xffffffffu, w, d);
            if (lane >= d) w += y;
        }
        warp_sums[lane] = w;
    }
    __syncthreads();
    int base = (x - s) + (warp > 0 ? warp_sums[warp - 1] : 0);
    if (i0     < NPADN) g_off[i0]     = base;
    if (i0 + 1 < NPADN) g_off[i0 + 1] = base + v0;
    if (i0 + 2 < NPADN) g_off[i0 + 2] = base + v0 + v1;
    if (t == 1023) g_off[NPADN] = warp_sums[31];
}

__global__ void k_edges2(const void* __restrict__ ei,
                         const float* __restrict__ ew) {
    int e = blockIdx.x * blockDim.x + threadIdx.x;
    if (e < NE) {
        int c = load_idx(ei, NE + e);
        int r = load_idx(ei, e);
        if ((unsigned)c < NPADN && (unsigned)r < NPADN) {
            int pos = g_off[c] + atomicAdd(&g_cur[c], 1);
            if ((unsigned)pos < NE) {
                g_bucket[pos] = r;
                g_wedge[pos]  = -g_dinv[r] * ew[e] * g_dinv[c];
            }
        }
    }
}

__global__ void k_T1(const float* __restrict__ h0) {
    int c = blockIdx.x;
    int d = threadIdx.x;
    float acc = 0.f;
    int p0 = g_off[c], p1 = g_off[c + 1];
    for (int p = p0; p < p1; p++)
        acc = fmaf(g_wedge[p], h0[g_bucket[p] * H2 + d], acc);
    __nv_bfloat16 h, l;
    split2(h0[c * H2 + d], h, l);
    g_Ahi[c * KCAT + H1 + d] = h;
    g_Alo[c * KCAT + H1 + d] = l;
    split2(acc, h, l);
    g_Ahi[c * KCAT + H1 + H2 + d] = h;
    g_Alo[c * KCAT + H1 + H2 + d] = l;
}

__global__ void k_buildB(const float* __restrict__ Wx,
                         const float* __restrict__ cw0,
                         const float* __restrict__ cw1) {
    int idx = blockIdx.x * blockDim.x + threadIdx.x;
    if (idx >= KCAT * KCAT) return;
    int j = idx >> 9;
    int k = idx & 511;
    int gg = j >> 7;
    int o  = j & 127;
    float v;
    if (k < H1)            v = Wx [gg * H1 * H2 + k * H2 + o];
    else if (k < H1 + H2)  v = cw0[gg * H2 * H2 + (k - H1) * H2 + o];
    else                   v = cw1[gg * H2 * H2 + (k - H1 - H2) * H2 + o];
    __nv_bfloat16 h, l; split2(v, h, l);
    g_BThi[idx] = h;
    g_BTlo[idx] = l;
}

// ================= GEMM1: mma.sync bf16 3-pass, 512 threads, BK=64 ==============
// CTA tile 128x256, 16 warps 4x4, warp tile 32x64. B-held fragment schedule.
__global__ void __launch_bounds__(512, 1) k_gemm1(const float* __restrict__ Xf) {
    extern __shared__ uint32_t smem[];
    uint32_t sbase = (uint32_t)__cvta_generic_to_shared(smem);

    int tid  = threadIdx.x;
    int warp = tid >> 5, lane = tid & 31;
    int wm = warp >> 2, wn = warp & 3;
    int g  = lane >> 2, t4 = lane & 3;
    int m0 = blockIdx.x * 128;
    int z  = blockIdx.y;
    int koff  = (z < 4) ? z * 1344 : 5376 + (z - 4) * 1408;
    int iters = ((z < 4) ? 1344 : 1408) / 64;

    float acc[2][8][4];
    #pragma unroll
    for (int a = 0; a < 2; a++)
        #pragma unroll
        for (int b = 0; b < 8; b++)
            #pragma unroll
            for (int c = 0; c < 4; c++) acc[a][b][c] = 0.f;

    // x loader: quarter-row (16 floats) per thread
    int arow = tid >> 2, aq = tid & 3;
    int xg = m0 + arow; bool xok = xg < NREAL;
    // B loader: one 128B row of one plane per thread
    int prow = tid & 255, ppl = (tid >> 8) & 1;

    int lrowA = (lane & 7) + ((lane >> 3) & 1) * 8;
    int lwrdA = (lane >> 4) * 4;
    int lrowB = (lane & 7) + (lane >> 4) * 8;
    int lwrdB = ((lane >> 3) & 1) * 4;

    float4 ra[4];
    const float4* X4 = (const float4*)Xf;

    auto issue_loads = [&](int it, int st) {
        int k0 = koff + it * 64;
        const __nv_bfloat16* src = (ppl ? g_wTlo : g_wThi) + (size_t)prow * FIN + k0;
        uint32_t dst = sbase + (st * WST + 2 * APL + ppl * BPL + prow * RSTR1) * 4;
        #pragma unroll
        for (int j = 0; j < 8; j++) CPA16(dst + j * 16, (const char*)src + j * 16, 16u);
        CPA_COMMIT();
        if (xok) {
            size_t b = (size_t)xg * (FIN / 4) + (k0 >> 2) + aq * 4;
            #pragma unroll
            for (int j = 0; j < 4; j++) ra[j] = X4[b + j];
        } else {
            #pragma unroll
            for (int j = 0; j < 4; j++) ra[j] = make_float4(0.f, 0.f, 0.f, 0.f);
        }
    };

    auto split_sts = [&](int st) {
        uint32_t hw[8], lw[8];
        #pragma unroll
        for (int j = 0; j < 4; j++) {
            split2x2(ra[j].x, ra[j].y, hw[2 * j],     lw[2 * j]);
            split2x2(ra[j].z, ra[j].w, hw[2 * j + 1], lw[2 * j + 1]);
        }
        uint32_t* dh = smem + st * WST + arow * RSTR1 + aq * 8;
        uint32_t* dl = dh + APL;
        *(uint4*)(dh)     = make_uint4(hw[0], hw[1], hw[2], hw[3]);
        *(uint4*)(dh + 4) = make_uint4(hw[4], hw[5], hw[6], hw[7]);
        *(uint4*)(dl)     = make_uint4(lw[0], lw[1], lw[2], lw[3]);
        *(uint4*)(dl + 4) = make_uint4(lw[4], lw[5], lw[6], lw[7]);
    };

    auto compute = [&](int st) {
        uint32_t base = (uint32_t)(st * WST);
        #pragma unroll
        for (int ks = 0; ks < 4; ks++) {
            uint32_t ah[2][4], al[2][4];
            #pragma unroll
            for (int mt = 0; mt < 2; mt++) {
                int r = wm * 32 + mt * 16 + lrowA;
                uint32_t oh = sbase + (base + r * RSTR1 + ks * 8 + lwrdA) * 4;
                uint32_t ol = sbase + (base + APL + r * RSTR1 + ks * 8 + lwrdA) * 4;
                LDMX4(ah[mt][0], ah[mt][1], ah[mt][2], ah[mt][3], oh);
                LDMX4(al[mt][0], al[mt][1], al[mt][2], al[mt][3], ol);
            }
            #pragma unroll
            for (int np = 0; np < 4; np++) {
                int r = wn * 64 + np * 16 + lrowB;
                uint32_t oh = sbase + (base + 2 * APL + r * RSTR1 + ks * 8 + lwrdB) * 4;
                uint32_t ol = sbase + (base + 2 * APL + BPL + r * RSTR1 + ks * 8 + lwrdB) * 4;
                uint32_t b0, b1, b2, b3;
                LDMX4(b0, b1, b2, b3, oh);          // B-hi: hh + lh
                #pragma unroll
                for (int mt = 0; mt < 2; mt++) {
                    mma_bf16(acc[mt][2 * np],     ah[mt], b0, b1);
                    mma_bf16(acc[mt][2 * np + 1], ah[mt], b2, b3);
                    mma_bf16(acc[mt][2 * np],     al[mt], b0, b1);
                    mma_bf16(acc[mt][2 * np + 1], al[mt], b2, b3);
                }
                LDMX4(b0, b1, b2, b3, ol);          // B-lo: hl
                #pragma unroll
                for (int mt = 0; mt < 2; mt++) {
                    mma_bf16(acc[mt][2 * np],     ah[mt], b0, b1);
                    mma_bf16(acc[mt][2 * np + 1], ah[mt], b2, b3);
                }
            }
        }
    };

    issue_loads(0, 0);
    split_sts(0);
    CPA_WAIT0();
    __syncthreads();

    for (int it = 0; it < iters; it++) {
        int cur = it & 1;
        if (it + 1 < iters) issue_loads(it + 1, cur ^ 1);
        compute(cur);
        if (it + 1 < iters) split_sts(cur ^ 1);
        CPA_WAIT0();
        __syncthreads();
    }

    float* C = g_part1 + (size_t)z * (MPAD * H1);
    #pragma unroll
    for (int mt = 0; mt < 2; mt++)
        #pragma unroll
        for (int nt = 0; nt < 8; nt++) {
            int r0 = m0 + wm * 32 + mt * 16 + g;
            int cc = wn * 64 + nt * 8 + t4 * 2;
            *(float2*)&C[(size_t)r0 * H1 + cc]       = make_float2(acc[mt][nt][0], acc[mt][nt][1]);
            *(float2*)&C[(size_t)(r0 + 8) * H1 + cc] = make_float2(acc[mt][nt][2], acc[mt][nt][3]);
        }
}

// ================= GEMM2: mma.sync bf16 3-pass, 256 threads ====================
__global__ void __launch_bounds__(256, 1) k_gemm2() {
    constexpr int K  = KCAT;
    constexpr int N  = KCAT;
    constexpr int MR = NPADN;

    extern __shared__ uint32_t smem[];
    uint32_t sbase = (uint32_t)__cvta_generic_to_shared(smem);

    int tid  = threadIdx.x;
    int warp = tid >> 5, lane = tid & 31;
    int wm = warp >> 1, wn = warp & 1;
    int g  = lane >> 2, t4 = lane & 3;
    int m0 = blockIdx.x * 128;
    int n0 = blockIdx.y * 128;
    int iters = K / 32;

    float acc[2][8][4];
    #pragma unroll
    for (int a = 0; a < 2; a++)
        #pragma unroll
        for (int b = 0; b < 8; b++)
            #pragma unroll
            for (int c = 0; c < 4; c++) acc[a][b][c] = 0.f;

    int prow  = tid & 127, ppl = tid >> 7;
    int ag    = m0 + prow;  bool aok = ag < MR;
    unsigned asz = aok ? 16u : 0u;

    int lrowA = (lane & 7) + ((lane >> 3) & 1) * 8;
    int lwrdA = (lane >> 4) * 4;
    int lrowB = (lane & 7) + (lane >> 4) * 8;
    int lwrdB = ((lane >> 3) & 1) * 4;

    auto issue_loads = [&](int it, int st) {
        int k0 = it * 32;
        {
            const __nv_bfloat16* src = (ppl ? g_BTlo : g_BThi) + (size_t)(n0 + prow) * K + k0;
            uint32_t dst = sbase + ((st * 4 + 2 + ppl) * PLANE + prow * RSTR) * 4;
            #pragma unroll
            for (int j = 0; j < 4; j++) CPA16(dst + j * 16, (const char*)src + j * 16, 16u);
        }
        {
            const __nv_bfloat16* src = (ppl ? g_Alo : g_Ahi) + (size_t)ag * K + k0;
            uint32_t dst = sbase + ((st * 4 + ppl) * PLANE + prow * RSTR) * 4;
            #pragma unroll
            for (int j = 0; j < 4; j++) CPA16(dst + j * 16, (const char*)src + j * 16, asz);
        }
        CPA_COMMIT();
    };

    auto compute = [&](int st) {
        #pragma unroll
        for (int ks = 0; ks < 2; ks++) {
            uint32_t ah[2][4], al[2][4];
            #pragma unroll
            for (int mt = 0; mt < 2; mt++) {
                int r = wm * 32 + mt * 16 + lrowA;
                uint32_t oh = sbase + ((st * 4 + 0) * PLANE + r * RSTR + ks * 8 + lwrdA) * 4;
                uint32_t ol = sbase + ((st * 4 + 1) * PLANE + r * RSTR + ks * 8 + lwrdA) * 4;
                LDMX4(ah[mt][0], ah[mt][1], ah[mt][2], ah[mt][3], oh);
                LDMX4(al[mt][0], al[mt][1], al[mt][2], al[mt][3], ol);
            }
            #pragma unroll
            for (int np = 0; np < 4; np++) {
                int r = wn * 64 + np * 16 + lrowB;
                uint32_t oh = sbase + ((st * 4 + 2) * PLANE + r * RSTR + ks * 8 + lwrdB) * 4;
                uint32_t ol = sbase + ((st * 4 + 3) * PLANE + r * RSTR + ks * 8 + lwrdB) * 4;
                uint32_t bh0, bh1, bh2, bh3, bl0, bl1, bl2, bl3;
                LDMX4(bh0, bh1, bh2, bh3, oh);
                LDMX4(bl0, bl1, bl2, bl3, ol);
                #pragma unroll
                for (int mt = 0; mt < 2; mt++) {
                    mma_bf16(acc[mt][2 * np],     ah[mt], bh0, bh1);
                    mma_bf16(acc[mt][2 * np],     ah[mt], bl0, bl1);
                    mma_bf16(acc[mt][2 * np],     al[mt], bh0, bh1);
                    mma_bf16(acc[mt][2 * np + 1], ah[mt], bh2, bh3);
                    mma_bf16(acc[mt][2 * np + 1], ah[mt], bl2, bl3);
                    mma_bf16(acc[mt][2 * np + 1], al[mt], bh2, bh3);
                }
            }
        }
    };

    issue_loads(0, 0);
    CPA_WAIT0();
    __syncthreads();

    for (int it = 0; it < iters; it++) {
        int cur = it & 1;
        if (it + 1 < iters) issue_loads(it + 1, cur ^ 1);
        compute(cur);
        CPA_WAIT0();
        __syncthreads();
    }

    float* C = g_acc2;
    #pragma unroll
    for (int mt = 0; mt < 2; mt++)
        #pragma unroll
        for (int nt = 0; nt < 8; nt++) {
            int r0 = m0 + wm * 32 + mt * 16 + g;
            int cc = n0 + wn * 64 + nt * 8 + t4 * 2;
            *(float2*)&C[(size_t)r0 * N + cc]       = make_float2(acc[mt][nt][0], acc[mt][nt][1]);
            *(float2*)&C[(size_t)(r0 + 8) * N + cc] = make_float2(acc[mt][nt][2], acc[mt][nt][3]);
        }
}

// ---------------- epilogue 1: reduce 6 partials + bias + relu + split ------------
__global__ void k_epi1(const float* __restrict__ fc0_b) {
    int idx = blockIdx.x * blockDim.x + threadIdx.x;
    if (idx >= NPADN * H1 / 4) return;
    int row = idx >> 6;
    int c4  = (idx & 63) * 4;
    float4 s = make_float4(0.f, 0.f, 0.f, 0.f);
    #pragma unroll
    for (int z = 0; z < 6; z++) {
        float4 p = *(const float4*)&g_part1[(size_t)z * MPAD * H1 + row * H1 + c4];
        s.x += p.x; s.y += p.y; s.z += p.z; s.w += p.w;
    }
    float4 b = *(const float4*)&fc0_b[c4];
    float z0 = fmaxf(s.x + b.x, 0.f), z1 = fmaxf(s.y + b.y, 0.f);
    float z2 = fmaxf(s.z + b.z, 0.f), z3 = fmaxf(s.w + b.w, 0.f);
    uint32_t h0, l0, h1, l1;
    split2x2(z0, z1, h0, l0);
    split2x2(z2, z3, h1, l1);
    *(uint2*)&g_Ahi[row * KCAT + c4] = make_uint2(h0, h1);
    *(uint2*)&g_Alo[row * KCAT + c4] = make_uint2(l0, l1);
}

// ---------------- LSTM pointwise + output projection -----------------------------
__global__ void k_lstm(const float* __restrict__ bg, const float* __restrict__ cb,
                       const float* __restrict__ c0,
                       const float* __restrict__ fc_w, const float* __restrict__ fc_b,
                       float* __restrict__ dout, int out_size) {
    __shared__ float red[4];
    int n = blockIdx.x;
    int o = threadIdx.x;
    const float* a = &g_acc2[(size_t)n * KCAT];
    float p0 = a[0 * H2 + o] + bg[0 * H2 + o] + cb[0 * H2 + o];
    float p1 = a[1 * H2 + o] + bg[1 * H2 + o] + cb[1 * H2 + o];
    float p2 = a[2 * H2 + o] + bg[2 * H2 + o] + cb[2 * H2 + o];
    float p3 = a[3 * H2 + o] + bg[3 * H2 + o] + cb[3 * H2 + o];
    float ig = sigmoidf_(p0);
    float fg = sigmoidf_(p1);
    float tg = tanhf(p2);
    float og = sigmoidf_(p3);
    float cn = fg * c0[n * H2 + o] + ig * tg;
    float hn = og * tanhf(cn);
    int hidx = NREAL + n * H2 + o;
    if (hidx < out_size) dout[hidx] = hn;

    float r = fmaxf(hn, 0.f) * fc_w[o];
    #pragma unroll
    for (int d = 16; d > 0; d >>= 1) r += __shfl_down_sync(0xffffffffu, r, d);
    int lane = o & 31, warp = o >> 5;
    if (lane == 0) red[warp] = r;
    __syncthreads();
    if (o == 0 && n < NREAL) {
        float s = red[0] + red[1] + red[2] + red[3] + fc_b[0];
        dout[n] = s;
    }
}

// ---------------- launch -----------------------------------------------------------
extern "C" void kernel_launch(void* const* d_in, const int* in_sizes, int n_in,
                              void* d_out, int out_size) {
    const float *x = nullptr, *ew = nullptr, *h0 = nullptr, *c0 = nullptr;
    const float *fc0w = nullptr, *fc0b = nullptr, *Wx = nullptr, *bg = nullptr;
    const float *cw0 = nullptr, *cw1 = nullptr, *cb = nullptr;
    const float *fcw = nullptr, *fcb = nullptr;
    const void* ei = nullptr;

    int pos384[2] = {-1, -1};
    int i256 = -1, iBigW = -1;

    for (int i = 0; i < n_in; i++) {
        int s = in_sizes[i];
        const void* p = d_in[i];
        if (s == NREAL * FIN)      x = (const float*)p;
        else if (s == 2 * NE)      ei = p;
        else if (s == NE)          ew = (const float*)p;
        else if (s == NPADN * H2)  { if (pos384[0] < 0) pos384[0] = i; else pos384[1] = i; }
        else if (s == FIN * H1)    { fc0w = (const float*)p; iBigW = i; }
        else if (s == H1)          { fc0b = (const float*)p; i256 = i; }
        else if (s == 4 * H1 * H2) Wx = (const float*)p;
        else if (s == 4 * H2)      { if (!bg) bg = (const float*)p; else cb = (const float*)p; }
        else if (s == 4 * H2 * H2) { if (!cw0) cw0 = (const float*)p; else cw1 = (const float*)p; }
        else if (s == H2)          fcw = (const float*)p;
        else if (s == 1)           fcb = (const float*)p;
    }

    bool sorted_order = (i256 >= 0 && iBigW >= 0 && i256 < iBigW);
    if (sorted_order) {
        c0 = (const float*)d_in[pos384[0]];
        h0 = (const float*)d_in[pos384[1]];
    } else {
        h0 = (const float*)d_in[pos384[0]];
        c0 = (const float*)d_in[pos384[1]];
    }

    float* out = (float*)d_out;

    // side stream + events, created once on the first (non-capture) call
    static cudaStream_t s1 = nullptr;
    static cudaEvent_t ev0 = nullptr, ev1 = nullptr;
    if (!s1) {
        cudaStreamCreateWithFlags(&s1, cudaStreamNonBlocking);
        cudaEventCreateWithFlags(&ev0, cudaEventDisableTiming);
        cudaEventCreateWithFlags(&ev1, cudaEventDisableTiming);
    }

    cudaFuncSetAttribute(k_gemm1, cudaFuncAttributeMaxDynamicSharedMemorySize, SMEM1);
    cudaFuncSetAttribute(k_gemm2, cudaFuncAttributeMaxDynamicSharedMemorySize, SMEMSZ);

    // main stream (0): conversions + GEMM1 chain
    k_probe_zero<<<(NPADN + 255) / 256, 256>>>(ei);
    cudaEventRecord(ev0, 0);
    cudaStreamWaitEvent(s1, ev0, 0);

    // side stream: graph preprocessing (independent of GEMM1)
    k_edges1<<<(NE / 2 + 255) / 256, 256, 0, s1>>>(ei, ew);
    k_scan<<<1, 1024, 0, s1>>>();
    k_edges2<<<(NE + 255) / 256, 256, 0, s1>>>(ei, ew);
    k_T1<<<NPADN, H2, 0, s1>>>(h0);
    cudaEventRecord(ev1, s1);

    // main stream continues
    k_convW<<<dim3(FIN / 32, H1 / 32), 256>>>(fc0w);
    k_buildB<<<(KCAT * KCAT + 255) / 256, 256>>>(Wx, cw0, cw1);
    k_gemm1<<<dim3(24, 6), 512, SMEM1>>>(x);
    k_epi1<<<(NPADN * H1 / 4 + 255) / 256, 256>>>(fc0b);
    cudaStreamWaitEvent(0, ev1, 0);           // join: gemm2 needs T1's A-cat cols
    k_gemm2<<<dim3(24, 4), 256, SMEMSZ>>>();
    k_lstm<<<NPADN, H2>>>(bg, cb, c0, fcw, fcb, out, out_size);
}

// round 15
// speedup vs baseline: 1.3120x; 1.3120x over previous
#include <cuda_runtime.h>
#include <cuda_bf16.h>
#include <cstdint>

#define NREAL 2800
#define NPADN 3000
#define MPAD  3072
#define FIN   8192
#define H1    256
#define H2    128
#define NE    179200
#define KCAT  512

// ---- GEMM constants (BK=32 everywhere; R13-proven) ----
#define RSTR  20
#define PLANE (128 * RSTR)
#define SMEMSZ (2 * 4 * PLANE * 4)  // 80KB (GEMM2)
#define APLANE (128 * RSTR)         // 2560 words
#define BPLANE (256 * RSTR)         // 5120 words
#define WSTAGE (2 * APLANE + 2 * BPLANE)   // 15360 words = 60KB
#define SMEM1  (2 * WSTAGE * 4)     // 120KB (GEMM1)

// ---------------- scratch (device-code references only!) --------------------
__device__ __align__(16) float g_part1[6 * MPAD * H1];
__device__ __align__(16) float g_acc2[MPAD * KCAT];
__device__ __align__(16) __nv_bfloat16 g_wThi[H1 * FIN];
__device__ __align__(16) __nv_bfloat16 g_wTlo[H1 * FIN];
__device__ __align__(16) __nv_bfloat16 g_Ahi[NPADN * KCAT];
__device__ __align__(16) __nv_bfloat16 g_Alo[NPADN * KCAT];
__device__ __align__(16) __nv_bfloat16 g_BThi[KCAT * KCAT];
__device__ __align__(16) __nv_bfloat16 g_BTlo[KCAT * KCAT];
__device__ __align__(16) float g_deg[NPADN];
__device__ __align__(16) float g_dinv[NPADN];
__device__ __align__(16) float g_wedge[NE];
__device__ __align__(16) int   g_cnt[NPADN];
__device__ __align__(16) int   g_cur[NPADN];
__device__ __align__(16) int   g_off[NPADN + 4];
__device__ __align__(16) int   g_bucket[NE];
__device__ int g_is32;

// ---------------- helpers ----------------------------------------------------
__device__ __forceinline__ float sigmoidf_(float x) { return 1.0f / (1.0f + expf(-x)); }

__device__ __forceinline__ void split2(float v, __nv_bfloat16& h, __nv_bfloat16& l) {
    h = __float2bfloat16_rn(v);
    l = __float2bfloat16_rn(v - __bfloat162float(h));
}
__device__ __forceinline__ void split2x2(float a, float b, uint32_t& h2, uint32_t& l2) {
    __nv_bfloat16 ha, la, hb, lb;
    split2(a, ha, la); split2(b, hb, lb);
    __nv_bfloat162 h = __halves2bfloat162(ha, hb);
    __nv_bfloat162 l = __halves2bfloat162(la, lb);
    h2 = *(uint32_t*)&h; l2 = *(uint32_t*)&l;
}
__device__ __forceinline__ int load_idx(const void* ei, int i) {
    if (g_is32) return ((const int*)ei)[i];
    return (int)((const long long*)ei)[i];
}
__device__ __forceinline__ void mma_bf16(float* d, const uint32_t* a,
                                         uint32_t b0, uint32_t b1) {
    asm volatile(
        "mma.sync.aligned.m16n8k16.row.col.f32.bf16.bf16.f32 "
        "{%0,%1,%2,%3}, {%4,%5,%6,%7}, {%8,%9}, {%0,%1,%2,%3};"
        : "+f"(d[0]), "+f"(d[1]), "+f"(d[2]), "+f"(d[3])
        : "r"(a[0]), "r"(a[1]), "r"(a[2]), "r"(a[3]), "r"(b0), "r"(b1));
}
#define LDMX4(r0, r1, r2, r3, a) \
    asm volatile("ldmatrix.sync.aligned.m8n8.x4.shared.b16 {%0,%1,%2,%3}, [%4];" \
                 : "=r"(r0), "=r"(r1), "=r"(r2), "=r"(r3) : "r"(a))
#define CPA16(dst, src, sz) \
    asm volatile("cp.async.ca.shared.global [%0], [%1], 16, %2;" \
                 :: "r"(dst), "l"(src), "r"(sz))
#define CPA_COMMIT() asm volatile("cp.async.commit_group;")
#define CPA_WAIT0()  asm volatile("cp.async.wait_group 0;")

// ---------------- probe + zero (fused) -----------------------------------------
__global__ void k_probe_zero(const void* p) {
    int i = blockIdx.x * blockDim.x + threadIdx.x;
    if (i < NPADN) { g_deg[i] = 0.f; g_cnt[i] = 0; g_cur[i] = 0; }
    if (blockIdx.x == 0) {
        __shared__ int any;
        if (threadIdx.x == 0) any = 0;
        __syncthreads();
        const int* q = (const int*)p;
        int v = 0;
        for (int j = threadIdx.x; j < 4096; j += blockDim.x) v |= q[2 * j + 1];
        if (v) atomicOr(&any, 1);
        __syncthreads();
        if (threadIdx.x == 0) g_is32 = (any != 0) ? 1 : 0;
    }
}

// fc0_w [FIN][H1] -> wT hi/lo [H1][FIN]
__global__ void k_convW(const float* __restrict__ w) {
    __shared__ float tile[32][33];
    int kb = blockIdx.x * 32, jb = blockIdx.y * 32;
    int tx = threadIdx.x & 31, ty = threadIdx.x >> 5;
    #pragma unroll
    for (int r = 0; r < 32; r += 8)
        tile[ty + r][tx] = w[(size_t)(kb + ty + r) * H1 + jb + tx];
    __syncthreads();
    #pragma unroll
    for (int r = 0; r < 32; r += 8) {
        float v = tile[tx][ty + r];
        __nv_bfloat16 h, l; split2(v, h, l);
        size_t o = (size_t)(jb + ty + r) * FIN + kb + tx;
        g_wThi[o] = h; g_wTlo[o] = l;
    }
}

// ---------------- graph preprocessing ------------------------------------------
__global__ void k_edges1(const void* __restrict__ ei,
                         const float* __restrict__ ew) {
    int base = (blockIdx.x * blockDim.x + threadIdx.x) * 2;
    #pragma unroll
    for (int j = 0; j < 2; j++) {
        int e = base + j;
        if (e < NE) {
            int r = load_idx(ei, e);
            int c = load_idx(ei, NE + e);
            if ((unsigned)r < NPADN) atomicAdd(&g_deg[r], ew[e]);
            if ((unsigned)c < NPADN) atomicAdd(&g_cnt[c], 1);
        }
    }
}

__global__ void k_scan() {
    int t = threadIdx.x;
    for (int i = t; i < NPADN; i += 1024) {
        float d = g_deg[i];
        g_dinv[i] = (d > 0.f) ? rsqrtf(d) : 0.f;
    }
    __shared__ int warp_sums[32];
    int i0 = t * 3;
    int v0 = (i0     < NPADN) ? g_cnt[i0]     : 0;
    int v1 = (i0 + 1 < NPADN) ? g_cnt[i0 + 1] : 0;
    int v2 = (i0 + 2 < NPADN) ? g_cnt[i0 + 2] : 0;
    int s = v0 + v1 + v2;
    int lane = t & 31, warp = t >> 5;
    int x = s;
    #pragma unroll
    for (int d = 1; d < 32; d <<= 1) {
        int y = __shfl_up_sync(0xffffffffu, x, d);
        if (lane >= d) x += y;
    }
    if (lane == 31) warp_sums[warp] = x;
    __syncthreads();
    if (warp == 0) {
        int w = warp_sums[lane];
        #pragma unroll
        for (int d = 1; d < 32; d <<= 1) {
            int y = __shfl_up_sync(0xffffffffu, w, d);
            if (lane >= d) w += y;
        }
        warp_sums[lane] = w;
    }
    __syncthreads();
    int base = (x - s) + (warp > 0 ? warp_sums[warp - 1] : 0);
    if (i0     < NPADN) g_off[i0]     = base;
    if (i0 + 1 < NPADN) g_off[i0 + 1] = base + v0;
    if (i0 + 2 < NPADN) g_off[i0 + 2] = base + v0 + v1;
    if (t == 1023) g_off[NPADN] = warp_sums[31];
}

__global__ void k_edges2(const void* __restrict__ ei,
                         const float* __restrict__ ew) {
    int e = blockIdx.x * blockDim.x + threadIdx.x;
    if (e < NE) {
        int c = load_idx(ei, NE + e);
        int r = load_idx(ei, e);
        if ((unsigned)c < NPADN && (unsigned)r < NPADN) {
            int pos = g_off[c] + atomicAdd(&g_cur[c], 1);
            if ((unsigned)pos < NE) {
                g_bucket[pos] = r;
                g_wedge[pos]  = -g_dinv[r] * ew[e] * g_dinv[c];
            }
        }
    }
}

__global__ void k_T1(const float* __restrict__ h0) {
    int c = blockIdx.x;
    int d = threadIdx.x;
    float acc = 0.f;
    int p0 = g_off[c], p1 = g_off[c + 1];
    for (int p = p0; p < p1; p++)
        acc = fmaf(g_wedge[p], h0[g_bucket[p] * H2 + d], acc);
    __nv_bfloat16 h, l;
    split2(h0[c * H2 + d], h, l);
    g_Ahi[c * KCAT + H1 + d] = h;
    g_Alo[c * KCAT + H1 + d] = l;
    split2(acc, h, l);
    g_Ahi[c * KCAT + H1 + H2 + d] = h;
    g_Alo[c * KCAT + H1 + H2 + d] = l;
}

__global__ void k_buildB(const float* __restrict__ Wx,
                         const float* __restrict__ cw0,
                         const float* __restrict__ cw1) {
    int idx = blockIdx.x * blockDim.x + threadIdx.x;
    if (idx >= KCAT * KCAT) return;
    int j = idx >> 9;
    int k = idx & 511;
    int gg = j >> 7;
    int o  = j & 127;
    float v;
    if (k < H1)            v = Wx [gg * H1 * H2 + k * H2 + o];
    else if (k < H1 + H2)  v = cw0[gg * H2 * H2 + (k - H1) * H2 + o];
    else                   v = cw1[gg * H2 * H2 + (k - H1 - H2) * H2 + o];
    __nv_bfloat16 h, l; split2(v, h, l);
    g_BThi[idx] = h;
    g_BTlo[idx] = l;
}

// ================= GEMM1: mma.sync bf16 3-pass, 512 threads, BK=32 (R13) ========
__global__ void __launch_bounds__(512, 1) k_gemm1(const float* __restrict__ Xf) {
    extern __shared__ uint32_t smem[];
    uint32_t sbase = (uint32_t)__cvta_generic_to_shared(smem);

    int tid  = threadIdx.x;
    int warp = tid >> 5, lane = tid & 31;
    int wm = warp >> 2, wn = warp & 3;
    int g  = lane >> 2, t4 = lane & 3;
    int m0 = blockIdx.x * 128;
    int z  = blockIdx.y;
    int koff  = (z < 4) ? z * 1344 : 5376 + (z - 4) * 1408;
    int iters = ((z < 4) ? 1344 : 1408) / 32;

    float acc[2][8][4];
    #pragma unroll
    for (int a = 0; a < 2; a++)
        #pragma unroll
        for (int b = 0; b < 8; b++)
            #pragma unroll
            for (int c = 0; c < 4; c++) acc[a][b][c] = 0.f;

    int arow = tid >> 2, aq = tid & 3;
    int xg = m0 + arow; bool xok = xg < NREAL;
    int prow = tid & 255, ppl = (tid >> 8) & 1;

    int lrowA = (lane & 7) + ((lane >> 3) & 1) * 8;
    int lwrdA = (lane >> 4) * 4;
    int lrowB = (lane & 7) + (lane >> 4) * 8;
    int lwrdB = ((lane >> 3) & 1) * 4;

    float4 ra[2];
    const float4* X4 = (const float4*)Xf;

    auto issue_loads = [&](int it, int st) {
        int k0 = koff + it * 32;
        const __nv_bfloat16* src = (ppl ? g_wTlo : g_wThi) + (size_t)prow * FIN + k0;
        uint32_t dst = sbase + (st * WSTAGE + 2 * APLANE + ppl * BPLANE + prow * RSTR) * 4;
        #pragma unroll
        for (int j = 0; j < 4; j++) CPA16(dst + j * 16, (const char*)src + j * 16, 16u);
        CPA_COMMIT();
        if (xok) {
            size_t b = (size_t)xg * (FIN / 4) + (k0 >> 2) + aq * 2;
            ra[0] = X4[b]; ra[1] = X4[b + 1];
        } else {
            ra[0] = make_float4(0.f, 0.f, 0.f, 0.f);
            ra[1] = make_float4(0.f, 0.f, 0.f, 0.f);
        }
    };

    auto split_sts = [&](int st) {
        uint32_t hw[4], lw[4];
        split2x2(ra[0].x, ra[0].y, hw[0], lw[0]);
        split2x2(ra[0].z, ra[0].w, hw[1], lw[1]);
        split2x2(ra[1].x, ra[1].y, hw[2], lw[2]);
        split2x2(ra[1].z, ra[1].w, hw[3], lw[3]);
        uint32_t* dh = smem + st * WSTAGE + arow * RSTR + aq * 4;
        *(uint4*)dh            = make_uint4(hw[0], hw[1], hw[2], hw[3]);
        *(uint4*)(dh + APLANE) = make_uint4(lw[0], lw[1], lw[2], lw[3]);
    };

    auto compute = [&](int st) {
        uint32_t base = (uint32_t)(st * WSTAGE);
        #pragma unroll
        for (int ks = 0; ks < 2; ks++) {
            uint32_t ah[2][4], al[2][4];
            #pragma unroll
            for (int mt = 0; mt < 2; mt++) {
                int r = wm * 32 + mt * 16 + lrowA;
                uint32_t oh = sbase + (base + r * RSTR + ks * 8 + lwrdA) * 4;
                uint32_t ol = sbase + (base + APLANE + r * RSTR + ks * 8 + lwrdA) * 4;
                LDMX4(ah[mt][0], ah[mt][1], ah[mt][2], ah[mt][3], oh);
                LDMX4(al[mt][0], al[mt][1], al[mt][2], al[mt][3], ol);
            }
            #pragma unroll
            for (int np = 0; np < 4; np++) {
                int r = wn * 64 + np * 16 + lrowB;
                uint32_t oh = sbase + (base + 2 * APLANE + r * RSTR + ks * 8 + lwrdB) * 4;
                uint32_t ol = sbase + (base + 2 * APLANE + BPLANE + r * RSTR + ks * 8 + lwrdB) * 4;
                uint32_t b0, b1, b2, b3;
                LDMX4(b0, b1, b2, b3, oh);          // B-hi: hh + lh
                #pragma unroll
                for (int mt = 0; mt < 2; mt++) {
                    mma_bf16(acc[mt][2 * np],     ah[mt], b0, b1);
                    mma_bf16(acc[mt][2 * np + 1], ah[mt], b2, b3);
                    mma_bf16(acc[mt][2 * np],     al[mt], b0, b1);
                    mma_bf16(acc[mt][2 * np + 1], al[mt], b2, b3);
                }
                LDMX4(b0, b1, b2, b3, ol);          // B-lo: hl
                #pragma unroll
                for (int mt = 0; mt < 2; mt++) {
                    mma_bf16(acc[mt][2 * np],     ah[mt], b0, b1);
                    mma_bf16(acc[mt][2 * np + 1], ah[mt], b2, b3);
                }
            }
        }
    };

    issue_loads(0, 0);
    split_sts(0);
    CPA_WAIT0();
    __syncthreads();

    for (int it = 0; it < iters; it++) {
        int cur = it & 1;
        if (it + 1 < iters) issue_loads(it + 1, cur ^ 1);
        compute(cur);
        if (it + 1 < iters) split_sts(cur ^ 1);
        CPA_WAIT0();
        __syncthreads();
    }

    float* C = g_part1 + (size_t)z * (MPAD * H1);
    #pragma unroll
    for (int mt = 0; mt < 2; mt++)
        #pragma unroll
        for (int nt = 0; nt < 8; nt++) {
            int r0 = m0 + wm * 32 + mt * 16 + g;
            int cc = wn * 64 + nt * 8 + t4 * 2;
            *(float2*)&C[(size_t)r0 * H1 + cc]       = make_float2(acc[mt][nt][0], acc[mt][nt][1]);
            *(float2*)&C[(size_t)(r0 + 8) * H1 + cc] = make_float2(acc[mt][nt][2], acc[mt][nt][3]);
        }
}

// ================= GEMM2: mma.sync bf16 3-pass, 256 threads ====================
__global__ void __launch_bounds__(256, 1) k_gemm2() {
    constexpr int K  = KCAT;
    constexpr int N  = KCAT;
    constexpr int MR = NPADN;

    extern __shared__ uint32_t smem[];
    uint32_t sbase = (uint32_t)__cvta_generic_to_shared(smem);

    int tid  = threadIdx.x;
    int warp = tid >> 5, lane = tid & 31;
    int wm = warp >> 1, wn = warp & 1;
    int g  = lane >> 2, t4 = lane & 3;
    int m0 = blockIdx.x * 128;
    int n0 = blockIdx.y * 128;
    int iters = K / 32;

    float acc[2][8][4];
    #pragma unroll
    for (int a = 0; a < 2; a++)
        #pragma unroll
        for (int b = 0; b < 8; b++)
            #pragma unroll
            for (int c = 0; c < 4; c++) acc[a][b][c] = 0.f;

    int prow  = tid & 127, ppl = tid >> 7;
    int ag    = m0 + prow;  bool aok = ag < MR;
    unsigned asz = aok ? 16u : 0u;

    int lrowA = (lane & 7) + ((lane >> 3) & 1) * 8;
    int lwrdA = (lane >> 4) * 4;
    int lrowB = (lane & 7) + (lane >> 4) * 8;
    int lwrdB = ((lane >> 3) & 1) * 4;

    auto issue_loads = [&](int it, int st) {
        int k0 = it * 32;
        {
            const __nv_bfloat16* src = (ppl ? g_BTlo : g_BThi) + (size_t)(n0 + prow) * K + k0;
            uint32_t dst = sbase + ((st * 4 + 2 + ppl) * PLANE + prow * RSTR) * 4;
            #pragma unroll
            for (int j = 0; j < 4; j++) CPA16(dst + j * 16, (const char*)src + j * 16, 16u);
        }
        {
            const __nv_bfloat16* src = (ppl ? g_Alo : g_Ahi) + (size_t)ag * K + k0;
            uint32_t dst = sbase + ((st * 4 + ppl) * PLANE + prow * RSTR) * 4;
            #pragma unroll
            for (int j = 0; j < 4; j++) CPA16(dst + j * 16, (const char*)src + j * 16, asz);
        }
        CPA_COMMIT();
    };

    auto compute = [&](int st) {
        #pragma unroll
        for (int ks = 0; ks < 2; ks++) {
            uint32_t ah[2][4], al[2][4];
            #pragma unroll
            for (int mt = 0; mt < 2; mt++) {
                int r = wm * 32 + mt * 16 + lrowA;
                uint32_t oh = sbase + ((st * 4 + 0) * PLANE + r * RSTR + ks * 8 + lwrdA) * 4;
                uint32_t ol = sbase + ((st * 4 + 1) * PLANE + r * RSTR + ks * 8 + lwrdA) * 4;
                LDMX4(ah[mt][0], ah[mt][1], ah[mt][2], ah[mt][3], oh);
                LDMX4(al[mt][0], al[mt][1], al[mt][2], al[mt][3], ol);
            }
            #pragma unroll
            for (int np = 0; np < 4; np++) {
                int r = wn * 64 + np * 16 + lrowB;
                uint32_t oh = sbase + ((st * 4 + 2) * PLANE + r * RSTR + ks * 8 + lwrdB) * 4;
                uint32_t ol = sbase + ((st * 4 + 3) * PLANE + r * RSTR + ks * 8 + lwrdB) * 4;
                uint32_t bh0, bh1, bh2, bh3, bl0, bl1, bl2, bl3;
                LDMX4(bh0, bh1, bh2, bh3, oh);
                LDMX4(bl0, bl1, bl2, bl3, ol);
                #pragma unroll
                for (int mt = 0; mt < 2; mt++) {
                    mma_bf16(acc[mt][2 * np],     ah[mt], bh0, bh1);
                    mma_bf16(acc[mt][2 * np],     ah[mt], bl0, bl1);
                    mma_bf16(acc[mt][2 * np],     al[mt], bh0, bh1);
                    mma_bf16(acc[mt][2 * np + 1], ah[mt], bh2, bh3);
                    mma_bf16(acc[mt][2 * np + 1], ah[mt], bl2, bl3);
                    mma_bf16(acc[mt][2 * np + 1], al[mt], bh2, bh3);
                }
            }
        }
    };

    issue_loads(0, 0);
    CPA_WAIT0();
    __syncthreads();

    for (int it = 0; it < iters; it++) {
        int cur = it & 1;
        if (it + 1 < iters) issue_loads(it + 1, cur ^ 1);
        compute(cur);
        CPA_WAIT0();
        __syncthreads();
    }

    float* C = g_acc2;
    #pragma unroll
    for (int mt = 0; mt < 2; mt++)
        #pragma unroll
        for (int nt = 0; nt < 8; nt++) {
            int r0 = m0 + wm * 32 + mt * 16 + g;
            int cc = n0 + wn * 64 + nt * 8 + t4 * 2;
            *(float2*)&C[(size_t)r0 * N + cc]       = make_float2(acc[mt][nt][0], acc[mt][nt][1]);
            *(float2*)&C[(size_t)(r0 + 8) * N + cc] = make_float2(acc[mt][nt][2], acc[mt][nt][3]);
        }
}

// ---------------- epilogue 1: reduce 6 partials + bias + relu + split ------------
__global__ void k_epi1(const float* __restrict__ fc0_b) {
    int idx = blockIdx.x * blockDim.x + threadIdx.x;
    if (idx >= NPADN * H1 / 4) return;
    int row = idx >> 6;
    int c4  = (idx & 63) * 4;
    float4 s = make_float4(0.f, 0.f, 0.f, 0.f);
    #pragma unroll
    for (int z = 0; z < 6; z++) {
        float4 p = *(const float4*)&g_part1[(size_t)z * MPAD * H1 + row * H1 + c4];
        s.x += p.x; s.y += p.y; s.z += p.z; s.w += p.w;
    }
    float4 b = *(const float4*)&fc0_b[c4];
    float z0 = fmaxf(s.x + b.x, 0.f), z1 = fmaxf(s.y + b.y, 0.f);
    float z2 = fmaxf(s.z + b.z, 0.f), z3 = fmaxf(s.w + b.w, 0.f);
    uint32_t h0, l0, h1, l1;
    split2x2(z0, z1, h0, l0);
    split2x2(z2, z3, h1, l1);
    *(uint2*)&g_Ahi[row * KCAT + c4] = make_uint2(h0, h1);
    *(uint2*)&g_Alo[row * KCAT + c4] = make_uint2(l0, l1);
}

// ---------------- LSTM pointwise + output projection -----------------------------
__global__ void k_lstm(const float* __restrict__ bg, const float* __restrict__ cb,
                       const float* __restrict__ c0,
                       const float* __restrict__ fc_w, const float* __restrict__ fc_b,
                       float* __restrict__ dout, int out_size) {
    __shared__ float red[4];
    int n = blockIdx.x;
    int o = threadIdx.x;
    const float* a = &g_acc2[(size_t)n * KCAT];
    float p0 = a[0 * H2 + o] + bg[0 * H2 + o] + cb[0 * H2 + o];
    float p1 = a[1 * H2 + o] + bg[1 * H2 + o] + cb[1 * H2 + o];
    float p2 = a[2 * H2 + o] + bg[2 * H2 + o] + cb[2 * H2 + o];
    float p3 = a[3 * H2 + o] + bg[3 * H2 + o] + cb[3 * H2 + o];
    float ig = sigmoidf_(p0);
    float fg = sigmoidf_(p1);
    float tg = tanhf(p2);
    float og = sigmoidf_(p3);
    float cn = fg * c0[n * H2 + o] + ig * tg;
    float hn = og * tanhf(cn);
    int hidx = NREAL + n * H2 + o;
    if (hidx < out_size) dout[hidx] = hn;

    float r = fmaxf(hn, 0.f) * fc_w[o];
    #pragma unroll
    for (int d = 16; d > 0; d >>= 1) r += __shfl_down_sync(0xffffffffu, r, d);
    int lane = o & 31, warp = o >> 5;
    if (lane == 0) red[warp] = r;
    __syncthreads();
    if (o == 0 && n < NREAL) {
        float s = red[0] + red[1] + red[2] + red[3] + fc_b[0];
        dout[n] = s;
    }
}

// ---------------- launch -----------------------------------------------------------
extern "C" void kernel_launch(void* const* d_in, const int* in_sizes, int n_in,
                              void* d_out, int out_size) {
    const float *x = nullptr, *ew = nullptr, *h0 = nullptr, *c0 = nullptr;
    const float *fc0w = nullptr, *fc0b = nullptr, *Wx = nullptr, *bg = nullptr;
    const float *cw0 = nullptr, *cw1 = nullptr, *cb = nullptr;
    const float *fcw = nullptr, *fcb = nullptr;
    const void* ei = nullptr;

    int pos384[2] = {-1, -1};
    int i256 = -1, iBigW = -1;

    for (int i = 0; i < n_in; i++) {
        int s = in_sizes[i];
        const void* p = d_in[i];
        if (s == NREAL * FIN)      x = (const float*)p;
        else if (s == 2 * NE)      ei = p;
        else if (s == NE)          ew = (const float*)p;
        else if (s == NPADN * H2)  { if (pos384[0] < 0) pos384[0] = i; else pos384[1] = i; }
        else if (s == FIN * H1)    { fc0w = (const float*)p; iBigW = i; }
        else if (s == H1)          { fc0b = (const float*)p; i256 = i; }
        else if (s == 4 * H1 * H2) Wx = (const float*)p;
        else if (s == 4 * H2)      { if (!bg) bg = (const float*)p; else cb = (const float*)p; }
        else if (s == 4 * H2 * H2) { if (!cw0) cw0 = (const float*)p; else cw1 = (const float*)p; }
        else if (s == H2)          fcw = (const float*)p;
        else if (s == 1)           fcb = (const float*)p;
    }

    bool sorted_order = (i256 >= 0 && iBigW >= 0 && i256 < iBigW);
    if (sorted_order) {
        c0 = (const float*)d_in[pos384[0]];
        h0 = (const float*)d_in[pos384[1]];
    } else {
        h0 = (const float*)d_in[pos384[0]];
        c0 = (const float*)d_in[pos384[1]];
    }

    float* out = (float*)d_out;

    // side stream (low priority) + events, created once (non-capture call)
    static cudaStream_t s1 = nullptr;
    static cudaEvent_t ev0 = nullptr, ev1 = nullptr;
    if (!s1) {
        int lo, hi;
        cudaDeviceGetStreamPriorityRange(&lo, &hi);   // lo = lowest priority value
        cudaStreamCreateWithPriority(&s1, cudaStreamNonBlocking, lo);
        cudaEventCreateWithFlags(&ev0, cudaEventDisableTiming);
        cudaEventCreateWithFlags(&ev1, cudaEventDisableTiming);
    }

    cudaFuncSetAttribute(k_gemm1, cudaFuncAttributeMaxDynamicSharedMemorySize, SMEM1);
    cudaFuncSetAttribute(k_gemm2, cudaFuncAttributeMaxDynamicSharedMemorySize, SMEMSZ);

    // main stream first: conversions + GEMM1 enqueued BEFORE side chain so the
    // one-wave GEMM1 gets dispatch priority; side kernels co-reside in the
    // free warp slots (gemm1 uses 512/2048 threads, side kernels use 0 smem).
    k_probe_zero<<<(NPADN + 255) / 256, 256>>>(ei);
    cudaEventRecord(ev0, 0);
    k_convW<<<dim3(FIN / 32, H1 / 32), 256>>>(fc0w);
    k_buildB<<<(KCAT * KCAT + 255) / 256, 256>>>(Wx, cw0, cw1);
    k_gemm1<<<dim3(24, 6), 512, SMEM1>>>(x);
    k_epi1<<<(NPADN * H1 / 4 + 255) / 256, 256>>>(fc0b);

    // side stream: graph preprocessing (depends only on probe_zero)
    cudaStreamWaitEvent(s1, ev0, 0);
    k_edges1<<<(NE / 2 + 255) / 256, 256, 0, s1>>>(ei, ew);
    k_scan<<<1, 1024, 0, s1>>>();
    k_edges2<<<(NE + 255) / 256, 256, 0, s1>>>(ei, ew);
    k_T1<<<NPADN, H2, 0, s1>>>(h0);
    cudaEventRecord(ev1, s1);

    // join: gemm2 needs epi1 (main) AND T1 (side)
    cudaStreamWaitEvent(0, ev1, 0);
    k_gemm2<<<dim3(24, 4), 256, SMEMSZ>>>();
    k_lstm<<<NPADN, H2>>>(bg, cb, c0, fcw, fcb, out, out_size);
}